// round 1
// baseline (speedup 1.0000x reference)
#include <cuda_runtime.h>
#include <math.h>

// DistillingLayer: conv1d(k=3, stride=2, pad=1, shared taps) -> ELU -> maxpool(k=3, stride=2, pad=1)
// x: (B=16, L=4096, D=512) f32, out: (B=16, Lp=1024, D=512) f32
//
// out[b, lp, d] = max(y[2lp-1], y[2lp], y[2lp+1])        (y[-1] = -inf)
// y[b, lc, d]   = ELU(w0*x[2lc-1] + w1*x[2lc] + w2*x[2lc+1] + bias)   (x[-1] = 0 pad)
//
// Each thread owns a float4 channel group and a strip of LP pool outputs.
// Registers carry x[4lp-1] and y[2lp-1] across iterations => exactly 4 new
// float4 loads + 1 float4 store per pool output (minimal DRAM traffic).

#define LP 8          // pool outputs per thread
#define D4 128        // D/4 float4 groups
#define L_IN 4096
#define LP_OUT 1024

__device__ __forceinline__ float elu1(float v) {
    return v > 0.0f ? v : expm1f(v);
}

__device__ __forceinline__ float4 conv_elu(float4 a, float4 b, float4 c,
                                           float w0, float w1, float w2, float bias) {
    float4 r;
    r.x = elu1(fmaf(w0, a.x, fmaf(w1, b.x, fmaf(w2, c.x, bias))));
    r.y = elu1(fmaf(w0, a.y, fmaf(w1, b.y, fmaf(w2, c.y, bias))));
    r.z = elu1(fmaf(w0, a.z, fmaf(w1, b.z, fmaf(w2, c.z, bias))));
    r.w = elu1(fmaf(w0, a.w, fmaf(w1, b.w, fmaf(w2, c.w, bias))));
    return r;
}

__device__ __forceinline__ float4 max4(float4 a, float4 b) {
    float4 r;
    r.x = fmaxf(a.x, b.x);
    r.y = fmaxf(a.y, b.y);
    r.z = fmaxf(a.z, b.z);
    r.w = fmaxf(a.w, b.w);
    return r;
}

__global__ void __launch_bounds__(256)
distill_fused_kernel(const float* __restrict__ x,
                     const float* __restrict__ w,
                     const float* __restrict__ bptr,
                     float* __restrict__ out) {
    const int d4 = threadIdx.x;                                // 0..127
    const int strip = blockIdx.x * blockDim.y + threadIdx.y;   // 0..127
    const int b = blockIdx.y;                                  // 0..15
    const int lp0 = strip * LP;

    const float w0 = __ldg(w);
    const float w1 = __ldg(w + 1);
    const float w2 = __ldg(w + 2);
    const float bias = __ldg(bptr);

    // float4 base pointers for this (batch, channel-group)
    const float4* xb = reinterpret_cast<const float4*>(x) + (size_t)b * L_IN * D4 + d4;
    float4* ob = reinterpret_cast<float4*>(out) + (size_t)b * LP_OUT * D4 + d4;

    float4 xprev;   // x[4*lp - 1] carried across iterations
    float4 ycarry;  // y[2*lp - 1] carried across iterations

    if (lp0 == 0) {
        // x[-1] is zero padding; y[-1] is -inf (maxpool pad excluded)
        xprev = make_float4(0.f, 0.f, 0.f, 0.f);
        ycarry = make_float4(-INFINITY, -INFINITY, -INFINITY, -INFINITY);
    } else {
        // prologue: y[2*lp0 - 1] needs x[4*lp0-3 .. 4*lp0-1]  (all in-range, lp0>=8)
        const int p = 4 * lp0 - 3;
        float4 a = xb[(size_t)p * D4];
        float4 c = xb[(size_t)(p + 1) * D4];
        float4 e = xb[(size_t)(p + 2) * D4];
        ycarry = conv_elu(a, c, e, w0, w1, w2, bias);
        xprev = e;
    }

#pragma unroll
    for (int i = 0; i < LP; i++) {
        const int lp = lp0 + i;
        const float4* xp = xb + (size_t)(4 * lp) * D4;
        // 4 independent loads (MLP=4): x[4lp], x[4lp+1], x[4lp+2], x[4lp+3]
        float4 x0 = xp[0];
        float4 x1 = xp[D4];
        float4 x2 = xp[2 * D4];
        float4 x3 = xp[3 * D4];

        float4 ye = conv_elu(xprev, x0, x1, w0, w1, w2, bias);  // y[2lp]
        float4 yo = conv_elu(x1, x2, x3, w0, w1, w2, bias);     // y[2lp+1]

        ob[(size_t)lp * D4] = max4(max4(ycarry, ye), yo);

        ycarry = yo;
        xprev = x3;
    }
}

extern "C" void kernel_launch(void* const* d_in, const int* in_sizes, int n_in,
                              void* d_out, int out_size) {
    const float* x = (const float*)d_in[0];
    const float* w = (const float*)d_in[1];
    const float* b = (const float*)d_in[2];
    float* out = (float*)d_out;

    // B=16, strips per batch = 1024/LP = 128, 2 strips per block
    dim3 block(D4, 2);
    dim3 grid((LP_OUT / LP) / 2, 16);
    distill_fused_kernel<<<grid, block>>>(x, w, b, out);
}

// round 2
// speedup vs baseline: 1.1972x; 1.1972x over previous
#include <cuda_runtime.h>
#include <math.h>

// DistillingLayer: conv1d(k=3, stride=2, pad=1, shared taps) -> ELU -> maxpool(k=3, stride=2, pad=1)
// x: (B=16, L=4096, D=512) f32, out: (B=16, Lp=1024, D=512) f32
//
// R1 change: libm expm1f (~40 instr, fma/alu pipes) -> __expf-1 (FMUL+MUFU.EX2+FADD+SEL).
// Kernel was issue-bound (issue=61.6%, DRAM=50%); this removes ~75% of the
// per-iteration instruction count to let the LDG.128 stream saturate HBM.

#define LP 8          // pool outputs per thread
#define D4 128        // D/4 float4 groups
#define L_IN 4096
#define LP_OUT 1024

__device__ __forceinline__ float elu1(float v) {
    // fast ELU: exp via MUFU.EX2; select keeps exact identity for v>0.
    float e = __expf(v) - 1.0f;
    return v > 0.0f ? v : e;
}

__device__ __forceinline__ float4 conv_elu(float4 a, float4 b, float4 c,
                                           float w0, float w1, float w2, float bias) {
    float4 r;
    r.x = elu1(fmaf(w0, a.x, fmaf(w1, b.x, fmaf(w2, c.x, bias))));
    r.y = elu1(fmaf(w0, a.y, fmaf(w1, b.y, fmaf(w2, c.y, bias))));
    r.z = elu1(fmaf(w0, a.z, fmaf(w1, b.z, fmaf(w2, c.z, bias))));
    r.w = elu1(fmaf(w0, a.w, fmaf(w1, b.w, fmaf(w2, c.w, bias))));
    return r;
}

__device__ __forceinline__ float4 max4(float4 a, float4 b) {
    float4 r;
    r.x = fmaxf(a.x, b.x);
    r.y = fmaxf(a.y, b.y);
    r.z = fmaxf(a.z, b.z);
    r.w = fmaxf(a.w, b.w);
    return r;
}

__global__ void __launch_bounds__(256)
distill_fused_kernel(const float* __restrict__ x,
                     const float* __restrict__ w,
                     const float* __restrict__ bptr,
                     float* __restrict__ out) {
    const int d4 = threadIdx.x;                                // 0..127
    const int strip = blockIdx.x * blockDim.y + threadIdx.y;   // 0..127
    const int b = blockIdx.y;                                  // 0..15
    const int lp0 = strip * LP;

    const float w0 = __ldg(w);
    const float w1 = __ldg(w + 1);
    const float w2 = __ldg(w + 2);
    const float bias = __ldg(bptr);

    // float4 base pointers for this (batch, channel-group)
    const float4* xb = reinterpret_cast<const float4*>(x) + (size_t)b * L_IN * D4 + d4;
    float4* ob = reinterpret_cast<float4*>(out) + (size_t)b * LP_OUT * D4 + d4;

    float4 xprev;   // x[4*lp - 1] carried across iterations
    float4 ycarry;  // y[2*lp - 1] carried across iterations

    if (lp0 == 0) {
        // x[-1] is zero padding; y[-1] is -inf (maxpool pad excluded)
        xprev = make_float4(0.f, 0.f, 0.f, 0.f);
        ycarry = make_float4(-INFINITY, -INFINITY, -INFINITY, -INFINITY);
    } else {
        // prologue: y[2*lp0 - 1] needs x[4*lp0-3 .. 4*lp0-1]  (all in-range, lp0>=8)
        const int p = 4 * lp0 - 3;
        float4 a = xb[(size_t)p * D4];
        float4 c = xb[(size_t)(p + 1) * D4];
        float4 e = xb[(size_t)(p + 2) * D4];
        ycarry = conv_elu(a, c, e, w0, w1, w2, bias);
        xprev = e;
    }

#pragma unroll
    for (int i = 0; i < LP; i++) {
        const int lp = lp0 + i;
        const float4* xp = xb + (size_t)(4 * lp) * D4;
        // 4 independent loads (MLP=4): x[4lp], x[4lp+1], x[4lp+2], x[4lp+3]
        float4 x0 = xp[0];
        float4 x1 = xp[D4];
        float4 x2 = xp[2 * D4];
        float4 x3 = xp[3 * D4];

        float4 ye = conv_elu(xprev, x0, x1, w0, w1, w2, bias);  // y[2lp]
        float4 yo = conv_elu(x1, x2, x3, w0, w1, w2, bias);     // y[2lp+1]

        ob[(size_t)lp * D4] = max4(max4(ycarry, ye), yo);

        ycarry = yo;
        xprev = x3;
    }
}

extern "C" void kernel_launch(void* const* d_in, const int* in_sizes, int n_in,
                              void* d_out, int out_size) {
    const float* x = (const float*)d_in[0];
    const float* w = (const float*)d_in[1];
    const float* b = (const float*)d_in[2];
    float* out = (float*)d_out;

    // B=16, strips per batch = 1024/LP = 128, 2 strips per block
    dim3 block(D4, 2);
    dim3 grid((LP_OUT / LP) / 2, 16);
    distill_fused_kernel<<<grid, block>>>(x, w, b, out);
}